// round 15
// baseline (speedup 1.0000x reference)
#include <cuda_runtime.h>
#include <math.h>

// LFQ: x [2,128,20] fp32 -> 256 tokens, D=20, K=2^20, TEMP=0.005.
// Out: q (5120 floats = sign(x)) then entro_mean, mean_entro, entro_loss,
// commit_loss.
//
// prob(code c|t) = e^{-r_t} * exp(-pen); pen = sum of w_d = 400|x_d| over
// dims flipped vs the hard sign code. Any flip of a dim with w_d >= 45
// underflows to 0 in fp32 (same underflow as the reference softmax), so
// survivor masks are SUBSETS OF THE SOFT-DIM SET {d : w_d < 45} (~1 dim per
// 10-dim half). R15: enumerate only those 2^popc(soft) subsets (~2-8 instead
// of 1024 masks/half), one WARP per token, no block barriers, grid = 32.
// CAS epoch-tag table with telescoping entropy (R12), last-warp ticket
// finalize. Epoch bump replaces any table repair across graph replays.

#define TOK    256
#define DIMS   20
#define THRESH 45.0f            // exp(-45)=2.9e-20, below fp32 softmax noise
#define MCAP   (1 << 20)
#define CAP    64               // survivor-list cap per half (sum<45 with >6
                                // dims needs avg |x|<0.019 -> unreachable)
#define FULLM  0xFFFFFFFFu

__device__ unsigned long long g_T[MCAP];  // {epoch:u32, val:f32}; zero at load
__device__ unsigned g_epoch = 1u;         // current-launch tag (tag 0 = clean)
__device__ unsigned g_ticket;             // finalize election; reset each run
__device__ double   g_accH;               // sum of per-token entropies
__device__ double   g_accC;               // sum of commit partials
__device__ double   g_accS;               // mean_probs entropy sum

__device__ __forceinline__ float entf(float v) {
    // f(v) = -(v/256)*log(v/256 + 1e-10); f(0) = 0
    float m = v * (1.0f / 256.0f);
    return (m > 0.f) ? -m * __logf(m + 1e-10f) : 0.f;
}

__global__ void __launch_bounds__(256, 4)
k_lfq(const float* __restrict__ x, float* __restrict__ outq,
      float* __restrict__ out4) {
    __shared__ int   sCA[8][CAP]; __shared__ float sVA[8][CAP];
    __shared__ int   sCB[8][CAP]; __shared__ float sVB[8][CAP];
    __shared__ int   s_nA[8], s_nB[8];

    const int tid  = threadIdx.x;
    const int w    = tid >> 5;               // warp = token within block
    const int lane = tid & 31;
    const int t    = blockIdx.x * 8 + w;

    if (lane == 0) { s_nA[w] = 0; s_nB[w] = 0; }

    // load x immediately; epoch load overlaps (same address, broadcast)
    float xv = (lane < DIMS) ? x[t * DIMS + lane] : 0.f;
    const unsigned ep = g_epoch;

    float sg = (xv > 0.f) ? 1.f : -1.f;
    float wv = (lane < DIMS) ? 400.0f * fabsf(xv) : 1e30f;
    if (lane < DIMS) outq[t * DIMS + lane] = sg;     // fire-and-forget

    unsigned bal = __ballot_sync(FULLM, (lane < DIMS) && (xv > 0.f));
    const unsigned hhi = bal & 0x3FFu;               // hard bits, dims 0..9
    const unsigned hlo = (bal >> 10) & 0x3FFu;       // hard bits, dims 10..19

    // per-token stats: H, commit, e^{-r} = prod 1/(1+e_d)
    float e  = __expf(-wv);                          // lanes>=20: e=0
    float rp = __logf(1.0f + e);                     //            rp=0
    float Hp = rp + wv * e / (1.0f + e);             //            Hp=0
    float cp = (lane < DIMS) ? (xv - sg) * (xv - sg) : 0.f;
    float pr = 1.0f / (1.0f + e);                    //            pr=1
    #pragma unroll
    for (int o = 16; o > 0; o >>= 1) {
        Hp += __shfl_down_sync(FULLM, Hp, o);
        cp += __shfl_down_sync(FULLM, cp, o);
        pr *= __shfl_down_sync(FULLM, pr, o);
    }
    const float er = __shfl_sync(FULLM, pr, 0);      // e^{-r_t}
    if (lane == 0) {
        atomicAdd(&g_accH, (double)Hp);              // REDG.64, no return
        atomicAdd(&g_accC, (double)cp);
    }

    // soft-dim sets per half (warp-uniform)
    unsigned sb  = __ballot_sync(FULLM, wv < THRESH);
    const unsigned Shi = sb & 0x3FFu;
    const unsigned Slo = (sb >> 10) & 0x3FFu;
    __syncwarp();

    // enumerate subsets of the soft set for each half; survivors -> smem list
    #pragma unroll
    for (int half = 0; half < 2; half++) {
        const unsigned S  = half ? Slo : Shi;
        const unsigned hc = half ? hlo : hhi;
        const int dbase   = half ? 10 : 0;
        const int nsub    = 1 << __popc(S);          // warp-uniform
        for (int base = 0; base < nsub; base += 32) {
            int sub = base + lane;
            unsigned s = S, mask = 0;
            float pen = 0.f;
            int bit = 0;
            while (s) {                              // warp-uniform trip count
                int d = __ffs(s) - 1; s &= s - 1;
                float wd = __shfl_sync(FULLM, wv, d + dbase);
                if ((sub >> bit) & 1) { pen += wd; mask |= 1u << d; }
                bit++;
            }
            if (sub < nsub && pen < THRESH) {
                if (half == 0) {
                    int p = atomicAdd(&s_nA[w], 1);
                    if (p < CAP) { sCA[w][p] = (int)(hhi ^ mask); sVA[w][p] = __expf(-pen); }
                } else {
                    int p = atomicAdd(&s_nB[w], 1);
                    if (p < CAP) { sCB[w][p] = (int)(hc ^ mask); sVB[w][p] = __expf(-pen); }
                }
            }
        }
    }
    __syncwarp();

    // cross-product CAS scatter with telescoping entropy contribution
    const int na = min(s_nA[w], CAP), nb = min(s_nB[w], CAP);
    const int total = na * nb;
    float ds = 0.f;
    for (int k = lane; k < total; k += 32) {
        int i = k / nb, j = k - i * nb;
        float v = er * sVA[w][i] * sVB[w][j];
        if (v > 0.f) {
            unsigned long long* slot = &g_T[sCA[w][i] * 1024 + sCB[w][j]];
            unsigned long long cur = __ldcg(slot);   // L2-fresh guess
            for (;;) {
                float oldv = ((unsigned)(cur >> 32) == ep)
                               ? __uint_as_float((unsigned)cur) : 0.f;
                float newv = oldv + v;
                unsigned long long des =
                    ((unsigned long long)ep << 32) | __float_as_uint(newv);
                unsigned long long prev = atomicCAS(slot, cur, des);
                if (prev == cur) {                   // committed
                    ds += entf(newv) - entf(oldv);   // telescopes to f(final)
                    break;
                }
                cur = prev;                          // collision: retry
            }
        }
    }

    // warp-reduce entropy partial; per-warp ticket elects the finalizer
    #pragma unroll
    for (int o = 16; o > 0; o >>= 1)
        ds += __shfl_down_sync(FULLM, ds, o);
    if (lane == 0) {
        atomicAdd(&g_accS, (double)ds);
        __threadfence();                             // release partials
        unsigned tk = atomicAdd(&g_ticket, 1u);
        if (tk == TOK - 1u) {                        // 256 warps total
            __threadfence();                         // acquire all partials
            double vh = *(volatile double*)&g_accH;
            double vc = *(volatile double*)&g_accC;
            double vs = *(volatile double*)&g_accS;
            double em = vh * (1.0 / 256.0);          // entro_mean_s
            out4[0] = (float)em;
            out4[1] = (float)vs;                     // mean_entro
            out4[2] = (float)(em - vs);              // entro_loss (ALPHA=1)
            out4[3] = (float)(vc * (1.0 / 5120.0));  // commit_loss
            g_ticket = 0u;                           // reset for replay
            g_accH = 0.0; g_accC = 0.0; g_accS = 0.0;
            g_epoch = ep + 1u;                       // invalidate table
        }
    }
}

extern "C" void kernel_launch(void* const* d_in, const int* in_sizes, int n_in,
                              void* d_out, int out_size) {
    const float* x = (const float*)d_in[0];
    float* out = (float*)d_out;
    int qn = in_sizes[0];                            // 5120

    k_lfq<<<32, 256>>>(x, out, out + qn);
}